// round 1
// baseline (speedup 1.0000x reference)
#include <cuda_runtime.h>
#include <math.h>

#define BB 16
#define TT 60
#define NCLS 80

__constant__ float c_anch[9][2] = {
    {12.f,16.f},{19.f,36.f},{40.f,28.f},{36.f,75.f},{76.f,55.f},
    {72.f,146.f},{142.f,110.f},{192.f,243.f},{459.f,401.f}};

// Per-(level,b,t) precomputed label data
__device__ float4 g_box[3*BB*TT];     // tx,ty,tw,th
__device__ int    g_key[3*BB*TT];     // packed (anchor<<20 | row<<10 | col), -1 if unmatched
__device__ int    g_valid[3*BB*TT];
__device__ float  g_vec[3*BB*TT*5];   // scale, fx, fy, lw, lh
__device__ int    g_cls[3*BB*TT];
__device__ int    g_hm[3*BB];         // has_match per (level,b)
__device__ double g_acc[5];           // xy, wh, obj, cls, l2

__device__ __forceinline__ float sigm(float x) { return 1.0f/(1.0f+expf(-x)); }
__device__ __forceinline__ float clog(float x) { return fmaxf(logf(x), -100.0f); }

__global__ void init_k() {
    int t = threadIdx.x;
    if (t < 5) g_acc[t] = 0.0;
    if (t < 3*BB) g_hm[t] = 0;
}

__global__ void label_k(const float* __restrict__ labels) {
    int idx = blockIdx.x*blockDim.x + threadIdx.x;
    if (idx >= BB*TT) return;
    int b = idx / TT, t = idx - b*TT;
    const float* L = labels + idx*5;
    float l0=L[0], l1=L[1], l2=L[2], l3=L[3], l4=L[4];
    int valid = (l0+l1+l2+l3+l4) > 0.0f;
    const float strides[3] = {8.f, 16.f, 32.f};
    const int   fss[3]     = {76, 38, 19};
    for (int oid = 0; oid < 3; oid++) {
        float s = strides[oid];
        int fs = fss[oid];
        float tx = (l2 + l0) / (s*2.0f);
        float ty = (l3 + l1) / (s*2.0f);
        float tw = (l2 - l0) / s;
        float th = (l3 - l1) / s;
        int gi = (oid*BB + b)*TT + t;
        g_box[gi]   = make_float4(tx,ty,tw,th);
        g_valid[gi] = valid;
        int key = -1;
        if (valid) {
            float best = -3.0e38f; int bi = 0;
            float at_t = atanf(tw/th);
            for (int k = 0; k < 9; k++) {
                float aw = c_anch[k][0]/s, ah = c_anch[k][1]/s;
                float iw = fminf(tw, aw), ih = fminf(th, ah);
                float ai = (iw > 0.f && ih > 0.f) ? iw*ih : 0.f;
                float au = tw*th + aw*ah - ai;
                float iou = ai/au;
                float mw = fmaxf(tw,aw), mh = fmaxf(th,ah);
                float c2 = mw*mw + mh*mh + 1e-16f;
                float rho2 = ((tw-aw)*(tw-aw) + (th-ah)*(th-ah)) * 0.25f;
                float d = at_t - atanf(aw/ah);
                float v = (4.0f/(float)(M_PI*M_PI)) * d * d;
                float alpha = v / (1.0f - iou + v);
                float ciou = iou - (rho2/c2 + v*alpha);
                if (ciou > best) { best = ciou; bi = k; }
            }
            int best_n = bi % 3;
            if (bi / 3 == oid) {
                int ii = min(max((int)tx, 0), fs-1);  // col (from tx)
                int jj = min(max((int)ty, 0), fs-1);  // row (from ty)
                key = (best_n << 20) | (jj << 10) | ii;
                g_hm[oid*BB + b] = 1;
                float aw = c_anch[3*oid+best_n][0]/s;
                float ah = c_anch[3*oid+best_n][1]/s;
                float* V = g_vec + (size_t)gi*5;
                V[0] = sqrtf(2.0f - tw*th/(float)(fs*fs));
                V[1] = tx - truncf(tx);
                V[2] = ty - truncf(ty);
                V[3] = logf(tw/aw + 1e-16f);
                V[4] = logf(th/ah + 1e-16f);
                g_cls[gi] = (int)l4;
            }
        }
        g_key[gi] = key;
    }
}

__global__ __launch_bounds__(256) void level_k(
    const float* __restrict__ x, int fs, int bpp, int oid, float stride)
{
    __shared__ float4 sbox[TT];
    __shared__ int skey[TT];
    __shared__ int sval[TT];
    int fs2 = fs*fs;
    int plane = blockIdx.x / bpp;
    int tile  = blockIdx.x - plane*bpp;
    int b = plane / 3, a = plane - 3*b;
    int tid = threadIdx.x;
    int gbase = (oid*BB + b)*TT;
    if (tid < TT) {
        sbox[tid] = g_box[gbase+tid];
        skey[tid] = g_key[gbase+tid];
        sval[tid] = g_valid[gbase+tid];
    }
    __syncthreads();
    int hm = g_hm[oid*BB + b];
    float anw = c_anch[3*oid+a][0]/stride;
    float anh = c_anch[3*oid+a][1]/stride;

    float axy=0.f, awh=0.f, aobj=0.f, acls=0.f, al2=0.f;
    int p = tile*blockDim.x + tid;
    if (p < fs2) {
        int i = p / fs, j = p - i*fs;          // i = row, j = col
        int base = (b*255 + a*85)*fs2 + p;
        float o0 = x[base];
        float o1 = x[base +   fs2];
        float o2 = x[base + 2*fs2];
        float o3 = x[base + 3*fs2];
        float o4 = x[base + 4*fs2];
        float sx = sigm(o0), sy = sigm(o1), sobj = sigm(o4);
        float px = sx + (float)j;
        float py = sy + (float)i;
        float pw = expf(o2)*anw;
        float ph = expf(o3)*anh;
        float areap = pw*ph;
        float pl = px - 0.5f*pw, pr = px + 0.5f*pw;
        float pt = py - 0.5f*ph, pb = py + 0.5f*ph;
        int myKey = (a<<20)|(i<<10)|j;
        bool ign = false; int tm = -1;
        #pragma unroll 4
        for (int t = 0; t < TT; t++) {
            if (!sval[t]) continue;
            if (skey[t] == myKey) tm = t;   // last t wins (JAX scatter order)
            if (!ign) {
                float4 tb = sbox[t];
                float tlx = fmaxf(pl, tb.x - 0.5f*tb.z);
                float brx = fminf(pr, tb.x + 0.5f*tb.z);
                float tly = fmaxf(pt, tb.y - 0.5f*tb.w);
                float bry = fminf(pb, tb.y + 0.5f*tb.w);
                if (tlx < brx && tly < bry) {
                    float ai = (brx-tlx)*(bry-tly);
                    float iou = ai / (areap + tb.z*tb.w - ai);
                    if (iou > 0.5f) ign = true;
                }
            }
        }
        if (tm >= 0) {
            const float* V = g_vec + (size_t)(gbase+tm)*5;
            float sc = V[0], fx = V[1], fy = V[2], lw = V[3], lh = V[4];
            int cls = g_cls[gbase+tm];
            // obj: mask=1, target=1
            aobj += -clog(sobj);
            float dob = sobj - 1.f;
            al2 += dob*dob;
            // xy BCE weighted by scale^2
            float w = sc*sc;
            axy += -w*(fx*clog(sx) + (1.f-fx)*clog(1.f-sx));
            axy += -w*(fy*clog(sy) + (1.f-fy)*clog(1.f-sy));
            float dx = sx - fx, dy = sy - fy;
            al2 += dx*dx + dy*dy;
            // wh
            float dw = sc*(o2 - lw), dh = sc*(o3 - lh);
            awh += 0.5f*(dw*dw + dh*dh);
            al2 += dw*dw + dh*dh;
            // cls (only matched cells touch the 80 class channels)
            for (int c = 0; c < NCLS; c++) {
                float pc = sigm(x[base + (5+c)*fs2]);
                float tc = (c == cls) ? 1.f : 0.f;
                acls += -(tc*clog(pc) + (1.f-tc)*clog(1.f-pc));
                float dc = pc - tc;
                al2 += dc*dc;
            }
        } else {
            int om = hm ? (ign ? 0 : 1) : 1;
            if (om) {
                aobj += -clog(1.f - sobj);
                al2 += sobj*sobj;
            }
        }
    }
    // warp reduction + per-warp atomic into double accumulators
    unsigned m = 0xffffffffu;
    for (int off = 16; off; off >>= 1) {
        axy  += __shfl_down_sync(m, axy,  off);
        awh  += __shfl_down_sync(m, awh,  off);
        aobj += __shfl_down_sync(m, aobj, off);
        acls += __shfl_down_sync(m, acls, off);
        al2  += __shfl_down_sync(m, al2,  off);
    }
    if ((tid & 31) == 0) {
        atomicAdd(&g_acc[0], (double)axy);
        atomicAdd(&g_acc[1], (double)awh);
        atomicAdd(&g_acc[2], (double)aobj);
        atomicAdd(&g_acc[3], (double)acls);
        atomicAdd(&g_acc[4], (double)al2);
    }
}

__global__ void fin_k(float* out) {
    if (threadIdx.x == 0) {
        float xy  = (float)g_acc[0];
        float wh  = (float)g_acc[1];
        float obj = (float)g_acc[2];
        float cls = (float)g_acc[3];
        float l2  = (float)g_acc[4];
        out[0] = xy + wh + obj + cls;
        out[1] = xy;
        out[2] = wh;
        out[3] = obj;
        out[4] = cls;
        out[5] = l2;
    }
}

extern "C" void kernel_launch(void* const* d_in, const int* in_sizes, int n_in,
                              void* d_out, int out_size) {
    const float* x0     = (const float*)d_in[0];
    const float* x1     = (const float*)d_in[1];
    const float* x2     = (const float*)d_in[2];
    const float* labels = (const float*)d_in[3];
    float* out = (float*)d_out;

    init_k<<<1, 64>>>();
    label_k<<<(BB*TT + 255)/256, 256>>>(labels);
    {
        int fs = 76, bpp = (fs*fs + 255)/256;   // 23
        level_k<<<BB*3*bpp, 256>>>(x0, fs, bpp, 0, 8.f);
    }
    {
        int fs = 38, bpp = (fs*fs + 255)/256;   // 6
        level_k<<<BB*3*bpp, 256>>>(x1, fs, bpp, 1, 16.f);
    }
    {
        int fs = 19, bpp = (fs*fs + 255)/256;   // 2
        level_k<<<BB*3*bpp, 256>>>(x2, fs, bpp, 2, 32.f);
    }
    fin_k<<<1, 32>>>(out);
}

// round 2
// speedup vs baseline: 3.5085x; 3.5085x over previous
#include <cuda_runtime.h>
#include <math.h>

#define BB 16
#define TT 60
#define NCLS 80

__constant__ float c_anch[9][2] = {
    {12.f,16.f},{19.f,36.f},{40.f,28.f},{36.f,75.f},{76.f,55.f},
    {72.f,146.f},{142.f,110.f},{192.f,243.f},{459.f,401.f}};

__constant__ int   c_fs[3]   = {76,38,19};
__constant__ int   c_fs2[3]  = {5776,1444,361};
__constant__ int   c_bpp[3]  = {23,6,2};
__constant__ int   c_moff[3] = {0, 277248, 346560};   // match-map level offsets
__constant__ float c_str[3]  = {8.f,16.f,32.f};

#define MAP_TOTAL 363888   // 16*3*(5776+1444+361)

// scatter match map: per level-cell, max matched label index t (or -1)
__device__ int    g_match[MAP_TOTAL];
// compacted valid truth boxes per (oid,b):  (l,t,r,b) + area, in level cell units
__device__ float4 g_cbox[3*BB*TT];
__device__ float  g_carea[3*BB*TT];
__device__ int    g_nv[3*BB];
__device__ int    g_hm[3*BB];
// per matched (oid,b,t): scale, fx, fy, lw, lh + class
__device__ float  g_vec[3*BB*TT*5];
__device__ int    g_cls[3*BB*TT];
__device__ double g_acc[5];   // xy, wh, obj, cls, l2

__device__ __forceinline__ float sigm(float x) { return __fdividef(1.0f, 1.0f + __expf(-x)); }
__device__ __forceinline__ float clog(float x) { return fmaxf(__logf(x), -100.0f); }

__global__ void init_k() {
    int idx = blockIdx.x*256 + threadIdx.x;
    if (idx < MAP_TOTAL) g_match[idx] = -1;
    if (idx < 5) g_acc[idx] = 0.0;
    if (idx < 3*BB) { g_hm[idx] = 0; g_nv[idx] = 0; }
}

__global__ void label_k(const float* __restrict__ labels) {
    int idx = blockIdx.x*blockDim.x + threadIdx.x;
    if (idx >= BB*TT) return;
    int b = idx / TT, t = idx - b*TT;
    const float* L = labels + idx*5;
    float l0=L[0], l1=L[1], l2=L[2], l3=L[3], l4=L[4];
    int valid = (l0+l1+l2+l3+l4) > 0.0f;
    if (!valid) return;
    for (int oid = 0; oid < 3; oid++) {
        float s = c_str[oid];
        int fs = c_fs[oid], fs2 = c_fs2[oid];
        float tx = (l2 + l0) / (s*2.0f);
        float ty = (l3 + l1) / (s*2.0f);
        float tw = (l2 - l0) / s;
        float th = (l3 - l1) / s;
        int ob = oid*BB + b;
        // compacted ignore-test box
        int slot = atomicAdd(&g_nv[ob], 1);
        int ci = ob*TT + slot;
        g_cbox[ci]  = make_float4(tx - 0.5f*tw, ty - 0.5f*th, tx + 0.5f*tw, ty + 0.5f*th);
        g_carea[ci] = tw*th;
        // CIoU argmax over 9 anchors (per level, matching reference rounding)
        float best = -3.0e38f; int bi = 0;
        float at_t = atanf(tw/th);
        for (int k = 0; k < 9; k++) {
            float aw = c_anch[k][0]/s, ah = c_anch[k][1]/s;
            float iw = fminf(tw, aw), ih = fminf(th, ah);
            float ai = (iw > 0.f && ih > 0.f) ? iw*ih : 0.f;
            float au = tw*th + aw*ah - ai;
            float iou = ai/au;
            float mw = fmaxf(tw,aw), mh = fmaxf(th,ah);
            float c2 = mw*mw + mh*mh + 1e-16f;
            float rho2 = ((tw-aw)*(tw-aw) + (th-ah)*(th-ah)) * 0.25f;
            float d = at_t - atanf(aw/ah);
            float v = (4.0f/(float)(M_PI*M_PI)) * d * d;
            float alpha = v / (1.0f - iou + v);
            float ciou = iou - (rho2/c2 + v*alpha);
            if (ciou > best) { best = ciou; bi = k; }
        }
        int best_n = bi % 3;
        if (bi / 3 == oid) {
            int ii = min(max((int)tx, 0), fs-1);   // col
            int jj = min(max((int)ty, 0), fs-1);   // row
            atomicMax(&g_match[c_moff[oid] + (b*3 + best_n)*fs2 + jj*fs + ii], t);
            g_hm[ob] = 1;
            float aw = c_anch[3*oid+best_n][0]/s;
            float ah = c_anch[3*oid+best_n][1]/s;
            int gi = ob*TT + t;
            float* V = g_vec + (size_t)gi*5;
            V[0] = sqrtf(2.0f - tw*th/(float)(fs*fs));
            V[1] = tx - truncf(tx);
            V[2] = ty - truncf(ty);
            V[3] = __logf(tw/aw + 1e-16f);
            V[4] = __logf(th/ah + 1e-16f);
            g_cls[gi] = (int)l4;
        }
    }
}

__global__ __launch_bounds__(256) void fused_k(
    const float* __restrict__ x0, const float* __restrict__ x1, const float* __restrict__ x2)
{
    __shared__ float4 sbx[TT];
    __shared__ float  sar[TT];
    __shared__ float  red[8][5];

    int bid = blockIdx.x;
    int oid = (bid >= 1104) + (bid >= 1392);
    int fs  = c_fs[oid], fs2 = c_fs2[oid], bpp = c_bpp[oid];
    int rel = bid - ((oid == 0) ? 0 : (oid == 1) ? 1104 : 1392);
    int plane = rel / bpp;
    int tile  = rel - plane*bpp;
    int b = plane / 3, a = plane - 3*b;
    const float* x = (oid == 0) ? x0 : (oid == 1) ? x1 : x2;

    int tid = threadIdx.x;
    int ob  = oid*BB + b;
    int nv  = g_nv[ob];
    int hm  = g_hm[ob];
    if (tid < nv) {
        sbx[tid] = g_cbox[ob*TT + tid];
        sar[tid] = g_carea[ob*TT + tid];
    }
    __syncthreads();

    float anw = c_anch[3*oid+a][0] / c_str[oid];
    float anh = c_anch[3*oid+a][1] / c_str[oid];

    float axy=0.f, awh=0.f, aobj=0.f, acls=0.f, al2=0.f;
    int p = tile*256 + tid;
    if (p < fs2) {
        int i = p / fs, j = p - i*fs;          // i = row, j = col
        int base = (b*255 + a*85)*fs2 + p;
        float o0 = x[base];
        float o1 = x[base +   fs2];
        float o2 = x[base + 2*fs2];
        float o3 = x[base + 3*fs2];
        float o4 = x[base + 4*fs2];
        float sx = sigm(o0), sy = sigm(o1), sobj = sigm(o4);

        int m = g_match[c_moff[oid] + (b*3 + a)*fs2 + p];
        if (m >= 0) {
            // ---- matched cell: xy/wh/obj/cls losses, ignore loop irrelevant ----
            const float* V = g_vec + (size_t)(ob*TT + m)*5;
            float sc = V[0], fx = V[1], fy = V[2], lw = V[3], lh = V[4];
            int cls = g_cls[ob*TT + m];
            aobj += -clog(sobj);
            float dob = sobj - 1.f;
            al2 += dob*dob;
            float w = sc*sc;
            axy += -w*(fx*clog(sx) + (1.f-fx)*clog(1.f-sx));
            axy += -w*(fy*clog(sy) + (1.f-fy)*clog(1.f-sy));
            float dx = sx - fx, dy = sy - fy;
            al2 += dx*dx + dy*dy;
            float dw = sc*(o2 - lw), dh = sc*(o3 - lh);
            awh += 0.5f*(dw*dw + dh*dh);
            al2 += dw*dw + dh*dh;
            #pragma unroll 4
            for (int c = 0; c < NCLS; c++) {
                float pc = sigm(x[base + (5+c)*fs2]);
                float tc = (c == cls) ? 1.f : 0.f;
                acls += -(tc*clog(pc) + (1.f-tc)*clog(1.f-pc));
                float dc = pc - tc;
                al2 += dc*dc;
            }
        } else {
            int om = 1;
            if (hm) {
                // ---- ignore test: break at first IoU > 0.5, division-free ----
                float px = sx + (float)j;
                float py = sy + (float)i;
                float pw = __expf(o2)*anw;
                float ph = __expf(o3)*anh;
                float areap = pw*ph;
                float pl = px - 0.5f*pw, pr = px + 0.5f*pw;
                float pt = py - 0.5f*ph, pb = py + 0.5f*ph;
                for (int t = 0; t < nv; t++) {
                    float4 tb = sbx[t];
                    float tlx = fmaxf(pl, tb.x);
                    float tly = fmaxf(pt, tb.y);
                    float brx = fminf(pr, tb.z);
                    float bry = fminf(pb, tb.w);
                    float dxw = brx - tlx, dyh = bry - tly;
                    if (dxw > 0.f && dyh > 0.f) {
                        float ai = dxw*dyh;
                        // iou > 0.5  <=>  3*ai > areap + area_t
                        if (3.0f*ai > areap + sar[t]) { om = 0; break; }
                    }
                }
            }
            if (om) {
                aobj += -clog(1.f - sobj);
                al2  += sobj*sobj;
            }
        }
    }

    // ---- block reduction: warp shuffle, then smem, then 5 atomics/block ----
    unsigned msk = 0xffffffffu;
    for (int off = 16; off; off >>= 1) {
        axy  += __shfl_down_sync(msk, axy,  off);
        awh  += __shfl_down_sync(msk, awh,  off);
        aobj += __shfl_down_sync(msk, aobj, off);
        acls += __shfl_down_sync(msk, acls, off);
        al2  += __shfl_down_sync(msk, al2,  off);
    }
    int w = tid >> 5;
    if ((tid & 31) == 0) {
        red[w][0]=axy; red[w][1]=awh; red[w][2]=aobj; red[w][3]=acls; red[w][4]=al2;
    }
    __syncthreads();
    if (tid < 5) {
        float s = 0.f;
        #pragma unroll
        for (int k = 0; k < 8; k++) s += red[k][tid];
        atomicAdd(&g_acc[tid], (double)s);
    }
}

__global__ void fin_k(float* out) {
    if (threadIdx.x == 0) {
        float xy  = (float)g_acc[0];
        float wh  = (float)g_acc[1];
        float obj = (float)g_acc[2];
        float cls = (float)g_acc[3];
        float l2  = (float)g_acc[4];
        out[0] = xy + wh + obj + cls;
        out[1] = xy;
        out[2] = wh;
        out[3] = obj;
        out[4] = cls;
        out[5] = l2;
    }
}

extern "C" void kernel_launch(void* const* d_in, const int* in_sizes, int n_in,
                              void* d_out, int out_size) {
    const float* x0     = (const float*)d_in[0];
    const float* x1     = (const float*)d_in[1];
    const float* x2     = (const float*)d_in[2];
    const float* labels = (const float*)d_in[3];
    float* out = (float*)d_out;

    init_k<<<(MAP_TOTAL + 255)/256, 256>>>();
    label_k<<<(BB*TT + 255)/256, 256>>>(labels);
    fused_k<<<1488, 256>>>(x0, x1, x2);
    fin_k<<<1, 32>>>(out);
}

// round 3
// speedup vs baseline: 3.8452x; 1.0960x over previous
#include <cuda_runtime.h>
#include <math.h>

#define BB 16
#define TT 60
#define NCLS 80
#define NBLK 1488   // 16*3*23 + 16*3*6 + 16*3*2

__constant__ float c_anch[9][2] = {
    {12.f,16.f},{19.f,36.f},{40.f,28.f},{36.f,75.f},{76.f,55.f},
    {72.f,146.f},{142.f,110.f},{192.f,243.f},{459.f,401.f}};

__constant__ int   c_fs[3]   = {76,38,19};
__constant__ int   c_fs2[3]  = {5776,1444,361};
__constant__ int   c_bpp[3]  = {23,6,2};
__constant__ float c_str[3]  = {8.f,16.f,32.f};

__device__ double g_acc[5];   // xy, wh, obj, cls, l2   (zero-init; reset by last block)
__device__ int    g_cnt;      // block completion counter (zero-init; reset by last block)

__device__ __forceinline__ float sigm(float x) { return __fdividef(1.0f, 1.0f + __expf(-x)); }
__device__ __forceinline__ float clog(float x) { return fmaxf(__logf(x), -100.0f); }

__global__ __launch_bounds__(256) void yolo_k(
    const float* __restrict__ x0, const float* __restrict__ x1,
    const float* __restrict__ x2, const float* __restrict__ labels,
    float* __restrict__ out)
{
    __shared__ float4 sbx[TT];       // valid truth boxes (l,t,r,b) in cell units
    __shared__ float  sar[TT];       // their areas
    __shared__ int    spack[TT];     // matched: (key<<6)|t
    __shared__ float  svec[TT][6];   // matched: scale,fx,fy,lw,lh,cls
    __shared__ int    snv, snm;
    __shared__ float  red[8][5];

    int bid = blockIdx.x;
    int oid = (bid >= 1104) + (bid >= 1392);
    int fs  = c_fs[oid], fs2 = c_fs2[oid], bpp = c_bpp[oid];
    int rel = bid - ((oid == 0) ? 0 : (oid == 1) ? 1104 : 1392);
    int plane = rel / bpp;
    int tile  = rel - plane*bpp;
    int b = plane / 3, a = plane - 3*b;
    const float* x = (oid == 0) ? x0 : (oid == 1) ? x1 : x2;
    float s = c_str[oid];

    int tid = threadIdx.x;
    if (tid == 0) { snv = 0; snm = 0; }
    __syncthreads();

    // ---------- phase 1: per-block label preprocessing for this (oid, b) ----------
    if (tid < TT) {
        const float* L = labels + (b*TT + tid)*5;
        float l0=L[0], l1=L[1], l2=L[2], l3=L[3], l4=L[4];
        if ((l0+l1+l2+l3+l4) > 0.0f) {
            float tx = (l2 + l0) / (s*2.0f);
            float ty = (l3 + l1) / (s*2.0f);
            float tw = (l2 - l0) / s;
            float th = (l3 - l1) / s;
            int slot = atomicAdd(&snv, 1);
            sbx[slot] = make_float4(tx - 0.5f*tw, ty - 0.5f*th, tx + 0.5f*tw, ty + 0.5f*th);
            sar[slot] = tw*th;
            // CIoU argmax over 9 anchors
            float best = -3.0e38f; int bi = 0;
            float at_t = atanf(tw/th);
            #pragma unroll
            for (int k = 0; k < 9; k++) {
                float aw = c_anch[k][0]/s, ah = c_anch[k][1]/s;
                float iw = fminf(tw, aw), ih = fminf(th, ah);
                float ai = (iw > 0.f && ih > 0.f) ? iw*ih : 0.f;
                float au = tw*th + aw*ah - ai;
                float iou = ai/au;
                float mw = fmaxf(tw,aw), mh = fmaxf(th,ah);
                float c2 = mw*mw + mh*mh + 1e-16f;
                float rho2 = ((tw-aw)*(tw-aw) + (th-ah)*(th-ah)) * 0.25f;
                float d = at_t - atanf(aw/ah);
                float v = (4.0f/(float)(M_PI*M_PI)) * d * d;
                float alpha = v / (1.0f - iou + v);
                float ciou = iou - (rho2/c2 + v*alpha);
                if (ciou > best) { best = ciou; bi = k; }
            }
            int best_n = bi % 3;
            if (bi / 3 == oid) {
                int ii = min(max((int)tx, 0), fs-1);   // col
                int jj = min(max((int)ty, 0), fs-1);   // row
                int key = (best_n << 20) | (jj << 10) | ii;
                int ms = atomicAdd(&snm, 1);
                spack[ms] = (key << 6) | tid;
                float aw = c_anch[3*oid+best_n][0]/s;
                float ah = c_anch[3*oid+best_n][1]/s;
                svec[ms][0] = sqrtf(2.0f - tw*th/(float)(fs*fs));
                svec[ms][1] = tx - truncf(tx);
                svec[ms][2] = ty - truncf(ty);
                svec[ms][3] = __logf(tw/aw + 1e-16f);
                svec[ms][4] = __logf(th/ah + 1e-16f);
                svec[ms][5] = l4;
            }
        }
    }
    __syncthreads();
    int nv = snv, nm = snm;

    // ---------- phase 2: per-cell losses ----------
    float anw = c_anch[3*oid+a][0] / s;
    float anh = c_anch[3*oid+a][1] / s;
    float axy=0.f, awh=0.f, aobj=0.f, acls=0.f, al2=0.f;

    int p = tile*256 + tid;
    if (p < fs2) {
        int i = p / fs, j = p - i*fs;          // i = row, j = col
        int base = (b*255 + a*85)*fs2 + p;
        float o0 = x[base];
        float o1 = x[base +   fs2];
        float o2 = x[base + 2*fs2];
        float o3 = x[base + 3*fs2];
        float o4 = x[base + 4*fs2];
        float sx = sigm(o0), sy = sigm(o1), sobj = sigm(o4);

        // match scan: max t among entries with my key (JAX last-write-wins)
        int myKey = (a<<20)|(i<<10)|j;
        int mT = -1, mSlot = -1;
        for (int k = 0; k < nm; k++) {
            int pk = spack[k];
            if ((pk >> 6) == myKey && (pk & 63) > mT) { mT = pk & 63; mSlot = k; }
        }

        if (mSlot >= 0) {
            float sc = svec[mSlot][0], fx = svec[mSlot][1], fy = svec[mSlot][2];
            float lw = svec[mSlot][3], lh = svec[mSlot][4];
            int cls = (int)svec[mSlot][5];
            aobj += -clog(sobj);
            float dob = sobj - 1.f;
            al2 += dob*dob;
            float w = sc*sc;
            axy += -w*(fx*clog(sx) + (1.f-fx)*clog(1.f-sx));
            axy += -w*(fy*clog(sy) + (1.f-fy)*clog(1.f-sy));
            float dx = sx - fx, dy = sy - fy;
            al2 += dx*dx + dy*dy;
            float dw = sc*(o2 - lw), dh = sc*(o3 - lh);
            awh += 0.5f*(dw*dw + dh*dh);
            al2 += dw*dw + dh*dh;
            #pragma unroll 4
            for (int c = 0; c < NCLS; c++) {
                float pc = sigm(x[base + (5+c)*fs2]);
                float tc = (c == cls) ? 1.f : 0.f;
                acls += -(tc*clog(pc) + (1.f-tc)*clog(1.f-pc));
                float dc = pc - tc;
                al2 += dc*dc;
            }
        } else {
            int om = 1;
            if (nm > 0) {   // has_match for this (b, level)
                float px = sx + (float)j;
                float py = sy + (float)i;
                float pw = __expf(o2)*anw;
                float ph = __expf(o3)*anh;
                float areap = pw*ph;
                float pl = px - 0.5f*pw, pr = px + 0.5f*pw;
                float pt = py - 0.5f*ph, pb = py + 0.5f*ph;
                for (int t = 0; t < nv; t++) {
                    float4 tb = sbx[t];
                    float tlx = fmaxf(pl, tb.x);
                    float tly = fmaxf(pt, tb.y);
                    float brx = fminf(pr, tb.z);
                    float bry = fminf(pb, tb.w);
                    float dxw = brx - tlx, dyh = bry - tly;
                    if (dxw > 0.f && dyh > 0.f) {
                        float ai = dxw*dyh;
                        if (3.0f*ai > areap + sar[t]) { om = 0; break; }  // iou > 0.5
                    }
                }
            }
            if (om) {
                aobj += -clog(1.f - sobj);
                al2  += sobj*sobj;
            }
        }
    }

    // ---------- phase 3: block reduce + global accumulate + last-block finalize ----------
    unsigned msk = 0xffffffffu;
    for (int off = 16; off; off >>= 1) {
        axy  += __shfl_down_sync(msk, axy,  off);
        awh  += __shfl_down_sync(msk, awh,  off);
        aobj += __shfl_down_sync(msk, aobj, off);
        acls += __shfl_down_sync(msk, acls, off);
        al2  += __shfl_down_sync(msk, al2,  off);
    }
    int w = tid >> 5;
    if ((tid & 31) == 0) {
        red[w][0]=axy; red[w][1]=awh; red[w][2]=aobj; red[w][3]=acls; red[w][4]=al2;
    }
    __syncthreads();
    if (tid == 0) {
        float s0=0.f,s1=0.f,s2=0.f,s3=0.f,s4=0.f;
        #pragma unroll
        for (int k = 0; k < 8; k++) {
            s0 += red[k][0]; s1 += red[k][1]; s2 += red[k][2];
            s3 += red[k][3]; s4 += red[k][4];
        }
        atomicAdd(&g_acc[0], (double)s0);
        atomicAdd(&g_acc[1], (double)s1);
        atomicAdd(&g_acc[2], (double)s2);
        atomicAdd(&g_acc[3], (double)s3);
        atomicAdd(&g_acc[4], (double)s4);
        __threadfence();
        int old = atomicAdd(&g_cnt, 1);
        if (old == NBLK - 1) {
            float xy  = (float)g_acc[0];
            float wh  = (float)g_acc[1];
            float obj = (float)g_acc[2];
            float cls = (float)g_acc[3];
            float l2  = (float)g_acc[4];
            out[0] = xy + wh + obj + cls;
            out[1] = xy;
            out[2] = wh;
            out[3] = obj;
            out[4] = cls;
            out[5] = l2;
            // reset for next graph replay (maintains zero-init invariant)
            g_acc[0]=0.0; g_acc[1]=0.0; g_acc[2]=0.0; g_acc[3]=0.0; g_acc[4]=0.0;
            g_cnt = 0;
        }
    }
}

extern "C" void kernel_launch(void* const* d_in, const int* in_sizes, int n_in,
                              void* d_out, int out_size) {
    const float* x0     = (const float*)d_in[0];
    const float* x1     = (const float*)d_in[1];
    const float* x2     = (const float*)d_in[2];
    const float* labels = (const float*)d_in[3];
    float* out = (float*)d_out;
    yolo_k<<<NBLK, 256>>>(x0, x1, x2, labels, out);
}

// round 5
// speedup vs baseline: 3.9063x; 1.0159x over previous
#include <cuda_runtime.h>
#include <math.h>

#define BB 16
#define TT 60
#define NCLS 80
#define NBLK_B 1488   // 16*3*23 + 16*3*6 + 16*3*2

__constant__ float c_anch[9][2] = {
    {12.f,16.f},{19.f,36.f},{40.f,28.f},{36.f,75.f},{76.f,55.f},
    {72.f,146.f},{142.f,110.f},{192.f,243.f},{459.f,401.f}};

__constant__ int   c_fs[3]   = {76,38,19};
__constant__ int   c_fs2[3]  = {5776,1444,361};
__constant__ float c_str[3]  = {8.f,16.f,32.f};
__constant__ int   c_moff[3] = {0, 277248, 346560};

#define MAP_TOTAL 363888

__device__ unsigned char g_map[MAP_TOTAL];   // 1 = matched cell (zero-init; B resets)
__device__ float4 g_cbox[3*BB*TT];
__device__ float  g_carea[3*BB*TT];
__device__ int    g_nv[3*BB];
__device__ int    g_hm[3*BB];
__device__ double g_acc[5];                  // xy, wh, obj, cls, l2
__device__ int    g_cnt;

__device__ __forceinline__ float sigm(float x) { return __fdividef(1.0f, 1.0f + __expf(-x)); }
__device__ __forceinline__ float clog(float x) { return fmaxf(__logf(x), -100.0f); }

// ---------------- Kernel A: label prep + matched-cell losses ----------------
__global__ __launch_bounds__(256) void prep_k(
    const float* __restrict__ labels,
    const float* __restrict__ x0, const float* __restrict__ x1,
    const float* __restrict__ x2)
{
    __shared__ int   skey[TT];       // (a<<20)|(jj<<10)|ii
    __shared__ int   st_[TT];        // label index t
    __shared__ float svec[TT][6];    // scale,fx,fy,lw,lh,cls
    __shared__ int   snv, snm;
    __shared__ float red[8][5];

    int ob = blockIdx.x;             // 0..47
    int oid = ob >> 4, b = ob & 15;
    int fs = c_fs[oid], fs2 = c_fs2[oid];
    float s = c_str[oid];
    const float* x = (oid == 0) ? x0 : (oid == 1) ? x1 : x2;

    int tid = threadIdx.x, lane = tid & 31, wid = tid >> 5;
    if (tid == 0) { snv = 0; snm = 0; }
    __syncthreads();

    if (tid < TT) {
        const float* L = labels + (b*TT + tid)*5;
        float l0=L[0], l1=L[1], l2=L[2], l3=L[3], l4=L[4];
        if ((l0+l1+l2+l3+l4) > 0.0f) {
            float tx = (l2 + l0) / (s*2.0f);
            float ty = (l3 + l1) / (s*2.0f);
            float tw = (l2 - l0) / s;
            float th = (l3 - l1) / s;
            int slot = atomicAdd(&snv, 1);
            g_cbox[ob*TT + slot]  = make_float4(tx - 0.5f*tw, ty - 0.5f*th,
                                                tx + 0.5f*tw, ty + 0.5f*th);
            g_carea[ob*TT + slot] = tw*th;
            // CIoU argmax over 9 anchors
            float best = -3.0e38f; int bi = 0;
            float at_t = atanf(tw/th);
            #pragma unroll
            for (int k = 0; k < 9; k++) {
                float aw = c_anch[k][0]/s, ah = c_anch[k][1]/s;
                float iw = fminf(tw, aw), ih = fminf(th, ah);
                float ai = (iw > 0.f && ih > 0.f) ? iw*ih : 0.f;
                float au = tw*th + aw*ah - ai;
                float iou = ai/au;
                float mw = fmaxf(tw,aw), mh = fmaxf(th,ah);
                float c2 = mw*mw + mh*mh + 1e-16f;
                float rho2 = ((tw-aw)*(tw-aw) + (th-ah)*(th-ah)) * 0.25f;
                float d = at_t - atanf(aw/ah);
                float v = (4.0f/(float)(M_PI*M_PI)) * d * d;
                float alpha = v / (1.0f - iou + v);
                float ciou = iou - (rho2/c2 + v*alpha);
                if (ciou > best) { best = ciou; bi = k; }
            }
            int best_n = bi % 3;
            if (bi / 3 == oid) {
                int ii = min(max((int)tx, 0), fs-1);
                int jj = min(max((int)ty, 0), fs-1);
                int ms = atomicAdd(&snm, 1);
                skey[ms] = (best_n << 20) | (jj << 10) | ii;
                st_[ms]  = tid;
                float aw = c_anch[3*oid+best_n][0]/s;
                float ah = c_anch[3*oid+best_n][1]/s;
                svec[ms][0] = sqrtf(2.0f - tw*th/(float)(fs*fs));
                svec[ms][1] = tx - truncf(tx);
                svec[ms][2] = ty - truncf(ty);
                svec[ms][3] = __logf(tw/aw + 1e-16f);
                svec[ms][4] = __logf(th/ah + 1e-16f);
                svec[ms][5] = l4;
            }
        }
    }
    __syncthreads();
    int nv = snv, nm = snm;
    if (tid == 0) { g_nv[ob] = nv; g_hm[ob] = (nm > 0); }

    // matched-cell losses: one warp per winning slot (dedup: max t per key wins)
    float axy=0.f, awh=0.f, aobj=0.f, acls=0.f, al2=0.f;
    for (int ms = wid; ms < nm; ms += 8) {
        int key = skey[ms], myt = st_[ms];
        bool win = true;
        for (int k = 0; k < nm; k++)
            if (skey[k] == key && st_[k] > myt) { win = false; break; }
        if (!win) continue;   // warp-uniform
        int a  = key >> 20;
        int jj = (key >> 10) & 1023;
        int ii = key & 1023;
        int base = (b*255 + a*85)*fs2 + jj*fs + ii;
        if (lane == 0)
            g_map[c_moff[oid] + (b*3 + a)*fs2 + jj*fs + ii] = 1;
        float sc = svec[ms][0], fx = svec[ms][1], fy = svec[ms][2];
        float lw = svec[ms][3], lh = svec[ms][4];
        int cls = (int)svec[ms][5];
        // class loop spread across lanes
        for (int c = lane; c < NCLS; c += 32) {
            float pc = sigm(x[base + (5+c)*fs2]);
            float tc = (c == cls) ? 1.f : 0.f;
            acls += -(tc*clog(pc) + (1.f-tc)*clog(1.f-pc));
            float dc = pc - tc;
            al2 += dc*dc;
        }
        if (lane == 0) {
            float o0 = x[base];
            float o1 = x[base +   fs2];
            float o2 = x[base + 2*fs2];
            float o3 = x[base + 3*fs2];
            float o4 = x[base + 4*fs2];
            float sx = sigm(o0), sy = sigm(o1), sobj = sigm(o4);
            aobj += -clog(sobj);
            float dob = sobj - 1.f;
            al2 += dob*dob;
            float w = sc*sc;
            axy += -w*(fx*clog(sx) + (1.f-fx)*clog(1.f-sx));
            axy += -w*(fy*clog(sy) + (1.f-fy)*clog(1.f-sy));
            float dx = sx - fx, dy = sy - fy;
            al2 += dx*dx + dy*dy;
            float dw = sc*(o2 - lw), dh = sc*(o3 - lh);
            awh += 0.5f*(dw*dw + dh*dh);
            al2 += dw*dw + dh*dh;
        }
    }

    unsigned msk = 0xffffffffu;
    for (int off = 16; off; off >>= 1) {
        axy  += __shfl_down_sync(msk, axy,  off);
        awh  += __shfl_down_sync(msk, awh,  off);
        aobj += __shfl_down_sync(msk, aobj, off);
        acls += __shfl_down_sync(msk, acls, off);
        al2  += __shfl_down_sync(msk, al2,  off);
    }
    if (lane == 0) {
        red[wid][0]=axy; red[wid][1]=awh; red[wid][2]=aobj; red[wid][3]=acls; red[wid][4]=al2;
    }
    __syncthreads();
    if (tid < 5) {
        float t = 0.f;
        #pragma unroll
        for (int k = 0; k < 8; k++) t += red[k][tid];
        atomicAdd(&g_acc[tid], (double)t);
    }
}

// ---------------- Kernel B: per-cell obj loss with warp-culled ignore test ----------------
__global__ __launch_bounds__(256) void cell_k(
    const float* __restrict__ x0, const float* __restrict__ x1,
    const float* __restrict__ x2, float* __restrict__ out)
{
    __shared__ float4 sbx[TT];
    __shared__ float  sar[TT];
    __shared__ float  red[8][2];

    int bid = blockIdx.x;
    int oid = (bid >= 1104) + (bid >= 1392);
    int fs  = c_fs[oid], fs2 = c_fs2[oid];
    int bpp = (oid == 0) ? 23 : (oid == 1) ? 6 : 2;
    int rel = bid - ((oid == 0) ? 0 : (oid == 1) ? 1104 : 1392);
    int plane = rel / bpp;
    int tile  = rel - plane*bpp;
    int b = plane / 3, a = plane - 3*b;
    const float* x = (oid == 0) ? x0 : (oid == 1) ? x1 : x2;

    int tid = threadIdx.x, lane = tid & 31, wid = tid >> 5;
    int ob = oid*BB + b;
    int nv = g_nv[ob];
    int hm = g_hm[ob];
    if (tid < nv) {
        sbx[tid] = g_cbox[ob*TT + tid];
        sar[tid] = g_carea[ob*TT + tid];
    }
    __syncthreads();

    float anw = c_anch[3*oid+a][0] / c_str[oid];
    float anh = c_anch[3*oid+a][1] / c_str[oid];

    int p = tile*256 + tid;
    bool inb = p < fs2;
    int pc_ = inb ? p : (fs2 - 1);
    int i = pc_ / fs, j = pc_ - i*fs;
    int base = (b*255 + a*85)*fs2 + pc_;
    float o0 = x[base];
    float o1 = x[base +   fs2];
    float o2 = x[base + 2*fs2];
    float o3 = x[base + 3*fs2];
    float o4 = x[base + 4*fs2];

    int midx = c_moff[oid] + (b*3 + a)*fs2 + pc_;
    unsigned char m = g_map[midx];
    if (inb) g_map[midx] = 0;     // reset for next replay

    bool active = inb && (m == 0);
    float sobj = sigm(o4);
    float sx = sigm(o0), sy = sigm(o1);
    float px = sx + (float)j, py = sy + (float)i;
    float pw = __expf(o2)*anw, ph = __expf(o3)*anh;
    float areap = pw*ph;
    float pl = px - 0.5f*pw, pr = px + 0.5f*pw;
    float pt = py - 0.5f*ph, pb = py + 0.5f*ph;

    bool doIgn = active && hm;
    float bl = doIgn ? pl :  1e30f;
    float br_ = doIgn ? pr : -1e30f;
    float bt = doIgn ? pt :  1e30f;
    float bb_ = doIgn ? pb : -1e30f;
    unsigned msk = 0xffffffffu;
    #pragma unroll
    for (int off = 16; off; off >>= 1) {
        bl  = fminf(bl,  __shfl_xor_sync(msk, bl,  off));
        br_ = fmaxf(br_, __shfl_xor_sync(msk, br_, off));
        bt  = fminf(bt,  __shfl_xor_sync(msk, bt,  off));
        bb_ = fmaxf(bb_, __shfl_xor_sync(msk, bb_, off));
    }
    // candidate ballots: lane L tests boxes L and L+32 against warp bbox
    bool c0 = false, c1 = false;
    if (lane < nv) {
        float4 tb = sbx[lane];
        c0 = (tb.x < br_) && (tb.z > bl) && (tb.y < bb_) && (tb.w > bt);
    }
    if (lane + 32 < nv) {
        float4 tb = sbx[lane + 32];
        c1 = (tb.x < br_) && (tb.z > bl) && (tb.y < bb_) && (tb.w > bt);
    }
    unsigned m0 = __ballot_sync(msk, c0);
    unsigned m1 = __ballot_sync(msk, c1);

    int om = 1;
    if (doIgn) {
        unsigned mm = m0;
        while (mm) {
            int t = __ffs(mm) - 1; mm &= mm - 1;
            float4 tb = sbx[t];
            float dxw = fminf(pr, tb.z) - fmaxf(pl, tb.x);
            float dyh = fminf(pb, tb.w) - fmaxf(pt, tb.y);
            if (dxw > 0.f && dyh > 0.f && 3.0f*dxw*dyh > areap + sar[t]) { om = 0; break; }
        }
        mm = om ? m1 : 0u;
        while (mm) {
            int t = __ffs(mm) - 1 + 32; mm &= mm - 1;
            float4 tb = sbx[t];
            float dxw = fminf(pr, tb.z) - fmaxf(pl, tb.x);
            float dyh = fminf(pb, tb.w) - fmaxf(pt, tb.y);
            if (dxw > 0.f && dyh > 0.f && 3.0f*dxw*dyh > areap + sar[t]) { om = 0; break; }
        }
    }

    float aobj = 0.f, al2 = 0.f;
    if (active && om) {
        aobj = -clog(1.f - sobj);
        al2  = sobj*sobj;
    }

    #pragma unroll
    for (int off = 16; off; off >>= 1) {
        aobj += __shfl_down_sync(msk, aobj, off);
        al2  += __shfl_down_sync(msk, al2,  off);
    }
    if (lane == 0) { red[wid][0] = aobj; red[wid][1] = al2; }
    __syncthreads();
    if (tid == 0) {
        float s2 = 0.f, s4 = 0.f;
        #pragma unroll
        for (int k = 0; k < 8; k++) { s2 += red[k][0]; s4 += red[k][1]; }
        atomicAdd(&g_acc[2], (double)s2);
        atomicAdd(&g_acc[4], (double)s4);
        __threadfence();
        int old = atomicAdd(&g_cnt, 1);
        if (old == NBLK_B - 1) {
            float xy  = (float)g_acc[0];
            float wh  = (float)g_acc[1];
            float obj = (float)g_acc[2];
            float cls = (float)g_acc[3];
            float l2  = (float)g_acc[4];
            out[0] = xy + wh + obj + cls;
            out[1] = xy;
            out[2] = wh;
            out[3] = obj;
            out[4] = cls;
            out[5] = l2;
            g_acc[0]=0.0; g_acc[1]=0.0; g_acc[2]=0.0; g_acc[3]=0.0; g_acc[4]=0.0;
            g_cnt = 0;
        }
    }
}

extern "C" void kernel_launch(void* const* d_in, const int* in_sizes, int n_in,
                              void* d_out, int out_size) {
    const float* x0     = (const float*)d_in[0];
    const float* x1     = (const float*)d_in[1];
    const float* x2     = (const float*)d_in[2];
    const float* labels = (const float*)d_in[3];
    float* out = (float*)d_out;
    prep_k<<<48, 256>>>(labels, x0, x1, x2);
    cell_k<<<NBLK_B, 256>>>(x0, x1, x2, out);
}

// round 6
// speedup vs baseline: 6.1597x; 1.5769x over previous
#include <cuda_runtime.h>
#include <math.h>

#define BB 16
#define TT 60
#define NCLS 80
#define NBLK 1488   // 48*23 + 48*6 + 48*2

__constant__ float c_anch[9][2] = {
    {12.f,16.f},{19.f,36.f},{40.f,28.f},{36.f,75.f},{76.f,55.f},
    {72.f,146.f},{142.f,110.f},{192.f,243.f},{459.f,401.f}};

__device__ double g_acc[5];   // xy, wh, obj, cls, l2 (zero-init; last block resets)
__device__ int    g_cnt;      // zero-init; last block resets

struct Sh {
    float4 sbx[TT];        // valid truth boxes (l,t,r,b)
    float  sar[TT];        // areas
    int    skey[TT];       // matched: (a<<20)|(jj<<10)|ii
    int    st[TT];         // matched: label index t
    float  svec[TT][6];    // matched: scale,fx,fy,lw,lh,cls
    int    fent[TT];       // entries filtered to this block's tile
    float  satn[9];        // atan(anchor_w/anchor_h)
    int    snv, snm, snf;
    float  red[8][5];
};

__device__ __forceinline__ float sigm(float x) { return __fdividef(1.0f, 1.0f + __expf(-x)); }
__device__ __forceinline__ float clog(float x) { return fmaxf(__logf(x), -100.0f); }

template<int FS, int OID>
__device__ __forceinline__ void level_body(
    Sh* sh, int rel,
    const float* __restrict__ x, const float* __restrict__ labels,
    float& axy, float& awh, float& aobj, float& acls, float& al2)
{
    constexpr int   FS2    = FS*FS;
    constexpr int   BPP    = (FS2 + 255)/256;
    constexpr float S      = (OID==0) ? 8.f : (OID==1) ? 16.f : 32.f;
    constexpr float INV_S  = 1.f/S;
    constexpr float INV_2S = 1.f/(2.f*S);
    constexpr float INV_FS2 = 1.f/(float)FS2;

    int tid = threadIdx.x, lane = tid & 31;
    int plane = rel / BPP;
    int tile  = rel - plane*BPP;
    int b = plane / 3, a = plane - 3*b;

    if (tid == 0) { sh->snv = 0; sh->snm = 0; sh->snf = 0; }
    if (tid < 9)  sh->satn[tid] = atanf(c_anch[tid][0] / c_anch[tid][1]);
    __syncthreads();

    // ---------- phase 1: per-block label prep for this (OID, b) ----------
    if (tid < TT) {
        const float* L = labels + (b*TT + tid)*5;
        float l0=L[0], l1=L[1], l2=L[2], l3=L[3], l4=L[4];
        if ((l0+l1+l2+l3+l4) > 0.0f) {
            float tx = (l2 + l0)*INV_2S;
            float ty = (l3 + l1)*INV_2S;
            float tw = (l2 - l0)*INV_S;
            float th = (l3 - l1)*INV_S;
            int slot = atomicAdd(&sh->snv, 1);
            sh->sbx[slot] = make_float4(tx - 0.5f*tw, ty - 0.5f*th,
                                        tx + 0.5f*tw, ty + 0.5f*th);
            sh->sar[slot] = tw*th;
            float area_t = tw*th;
            float best = -3.0e38f; int bi = 0;
            float at_t = atanf(tw/th);
            #pragma unroll
            for (int k = 0; k < 9; k++) {
                float aw = c_anch[k][0]*INV_S, ah = c_anch[k][1]*INV_S;
                float iw = fminf(tw, aw), ih = fminf(th, ah);
                float ai = (iw > 0.f && ih > 0.f) ? iw*ih : 0.f;
                float iou = __fdividef(ai, area_t + aw*ah - ai);
                float mw = fmaxf(tw,aw), mh = fmaxf(th,ah);
                float c2 = mw*mw + mh*mh + 1e-16f;
                float rho2 = ((tw-aw)*(tw-aw) + (th-ah)*(th-ah)) * 0.25f;
                float d = at_t - sh->satn[k];
                float v = (4.0f/(float)(M_PI*M_PI)) * d * d;
                float ciou = iou - (__fdividef(rho2, c2) + v*__fdividef(v, 1.f - iou + v));
                if (ciou > best) { best = ciou; bi = k; }
            }
            int best_n = bi - (bi/3)*3;
            if (bi/3 == OID) {
                int ii = min(max((int)tx, 0), FS-1);
                int jj = min(max((int)ty, 0), FS-1);
                int ms = atomicAdd(&sh->snm, 1);
                sh->skey[ms] = (best_n << 20) | (jj << 10) | ii;
                sh->st[ms]   = tid;
                float aw = c_anch[3*OID+best_n][0]*INV_S;
                float ah = c_anch[3*OID+best_n][1]*INV_S;
                sh->svec[ms][0] = sqrtf(2.f - tw*th*INV_FS2);
                sh->svec[ms][1] = tx - truncf(tx);
                sh->svec[ms][2] = ty - truncf(ty);
                sh->svec[ms][3] = __logf(tw/aw + 1e-16f);
                sh->svec[ms][4] = __logf(th/ah + 1e-16f);
                sh->svec[ms][5] = l4;
            }
        }
    }
    __syncthreads();
    int nv = sh->snv, nm = sh->snm;
    int p0 = tile*256;

    // filter matched entries down to this block's (anchor, tile)
    if (tid < nm) {
        int key = sh->skey[tid];
        if ((key >> 20) == a) {
            int cell = ((key >> 10) & 1023)*FS + (key & 1023);
            if (cell >= p0 && cell < p0 + 256) {
                int f = atomicAdd(&sh->snf, 1);
                sh->fent[f] = tid;
            }
        }
    }
    __syncthreads();
    int nf = sh->snf;
    int hm = (nm > 0);

    // ---------- phase 2: per-cell ----------
    int p = p0 + tid;
    bool inb = (p < FS2);
    int pc_ = inb ? p : (FS2 - 1);
    int i = pc_ / FS, j = pc_ - i*FS;
    const float* xb = x + (size_t)(b*255 + a*85)*FS2 + pc_;
    float o0 = xb[0];
    float o1 = xb[FS2];
    float o2 = xb[2*FS2];
    float o3 = xb[3*FS2];
    float o4 = xb[4*FS2];
    float sobj = sigm(o4), sx = sigm(o0), sy = sigm(o1);

    // match resolve against tiny filtered list (last-wins = max t)
    int myKey = (a << 20) | (i << 10) | j;
    int mslot = -1, mT = -1;
    for (int f = 0; f < nf; f++) {
        int e = sh->fent[f];
        if (sh->skey[e] == myKey && sh->st[e] > mT) { mT = sh->st[e]; mslot = e; }
    }
    bool matched = inb && (mslot >= 0);
    unsigned full = 0xffffffffu;

    if (matched) {
        float sc = sh->svec[mslot][0], fx = sh->svec[mslot][1], fy = sh->svec[mslot][2];
        float lw = sh->svec[mslot][3], lh = sh->svec[mslot][4];
        aobj += -clog(sobj);
        float dob = sobj - 1.f;
        al2 += dob*dob;
        float w = sc*sc;
        axy += -w*(fx*clog(sx) + (1.f-fx)*clog(1.f-sx));
        axy += -w*(fy*clog(sy) + (1.f-fy)*clog(1.f-sy));
        float dx = sx - fx, dy = sy - fy;
        al2 += dx*dx + dy*dy;
        float dw = sc*(o2 - lw), dh = sc*(o3 - lh);
        awh += 0.5f*(dw*dw + dh*dh);
        al2 += dw*dw + dh*dh;
    }

    // warp-cooperative class loss for matched cells
    unsigned mball = __ballot_sync(full, matched);
    while (mball) {
        int src = __ffs(mball) - 1; mball &= mball - 1;
        int spc = __shfl_sync(full, pc_,   src);
        int sl  = __shfl_sync(full, mslot, src);
        int cls = (int)sh->svec[sl][5];
        const float* xc = x + (size_t)(b*255 + a*85)*FS2 + spc + 5*FS2;
        float oa  = xc[lane*FS2];
        float obv = xc[(lane+32)*FS2];
        float ocv = (lane < 16) ? xc[(lane+64)*FS2] : 0.f;
        {
            float pcv = sigm(oa);
            float tc = (lane == cls) ? 1.f : 0.f;
            acls += -(tc*clog(pcv) + (1.f-tc)*clog(1.f-pcv));
            float dc = pcv - tc; al2 += dc*dc;
        }
        {
            float pcv = sigm(obv);
            float tc = (lane + 32 == cls) ? 1.f : 0.f;
            acls += -(tc*clog(pcv) + (1.f-tc)*clog(1.f-pcv));
            float dc = pcv - tc; al2 += dc*dc;
        }
        if (lane < 16) {
            float pcv = sigm(ocv);
            float tc = (lane + 64 == cls) ? 1.f : 0.f;
            acls += -(tc*clog(pcv) + (1.f-tc)*clog(1.f-pcv));
            float dc = pcv - tc; al2 += dc*dc;
        }
    }

    // obj loss for unmatched cells (with ballot-culled ignore test)
    bool active = inb && !matched;
    int om = 1;
    if (hm) {
        float anw = c_anch[3*OID+a][0]*INV_S;
        float anh = c_anch[3*OID+a][1]*INV_S;
        float px = sx + (float)j, py = sy + (float)i;
        float pw = __expf(o2)*anw, ph = __expf(o3)*anh;
        float areap = pw*ph;
        float pl = px - 0.5f*pw, pr = px + 0.5f*pw;
        float pt = py - 0.5f*ph, pb = py + 0.5f*ph;
        bool doIgn = active;
        float bl  = doIgn ? pl :  1e30f;
        float br_ = doIgn ? pr : -1e30f;
        float bt  = doIgn ? pt :  1e30f;
        float bb_ = doIgn ? pb : -1e30f;
        #pragma unroll
        for (int off = 16; off; off >>= 1) {
            bl  = fminf(bl,  __shfl_xor_sync(full, bl,  off));
            br_ = fmaxf(br_, __shfl_xor_sync(full, br_, off));
            bt  = fminf(bt,  __shfl_xor_sync(full, bt,  off));
            bb_ = fmaxf(bb_, __shfl_xor_sync(full, bb_, off));
        }
        bool c0 = false, c1 = false;
        if (lane < nv) {
            float4 tb = sh->sbx[lane];
            c0 = (tb.x < br_) && (tb.z > bl) && (tb.y < bb_) && (tb.w > bt);
        }
        if (lane + 32 < nv) {
            float4 tb = sh->sbx[lane + 32];
            c1 = (tb.x < br_) && (tb.z > bl) && (tb.y < bb_) && (tb.w > bt);
        }
        unsigned m0 = __ballot_sync(full, c0);
        unsigned m1 = __ballot_sync(full, c1);
        if (doIgn) {
            unsigned mm = m0;
            while (mm) {
                int t = __ffs(mm) - 1; mm &= mm - 1;
                float4 tb = sh->sbx[t];
                float dxw = fminf(pr, tb.z) - fmaxf(pl, tb.x);
                float dyh = fminf(pb, tb.w) - fmaxf(pt, tb.y);
                if (dxw > 0.f && dyh > 0.f && 3.0f*dxw*dyh > areap + sh->sar[t]) { om = 0; break; }
            }
            mm = om ? m1 : 0u;
            while (mm) {
                int t = __ffs(mm) - 1 + 32; mm &= mm - 1;
                float4 tb = sh->sbx[t];
                float dxw = fminf(pr, tb.z) - fmaxf(pl, tb.x);
                float dyh = fminf(pb, tb.w) - fmaxf(pt, tb.y);
                if (dxw > 0.f && dyh > 0.f && 3.0f*dxw*dyh > areap + sh->sar[t]) { om = 0; break; }
            }
        }
    }
    if (active && om) {
        aobj += -clog(1.f - sobj);
        al2  += sobj*sobj;
    }
}

__global__ __launch_bounds__(256) void yolo_k(
    const float* __restrict__ x0, const float* __restrict__ x1,
    const float* __restrict__ x2, const float* __restrict__ labels,
    float* __restrict__ out)
{
    extern __shared__ char smem[];
    Sh* sh = (Sh*)smem;

    float axy=0.f, awh=0.f, aobj=0.f, acls=0.f, al2=0.f;
    int bid = blockIdx.x;
    if (bid < 1104)      level_body<76,0>(sh, bid,        x0, labels, axy, awh, aobj, acls, al2);
    else if (bid < 1392) level_body<38,1>(sh, bid - 1104, x1, labels, axy, awh, aobj, acls, al2);
    else                 level_body<19,2>(sh, bid - 1392, x2, labels, axy, awh, aobj, acls, al2);

    int tid = threadIdx.x, lane = tid & 31, wid = tid >> 5;
    unsigned full = 0xffffffffu;
    #pragma unroll
    for (int off = 16; off; off >>= 1) {
        axy  += __shfl_down_sync(full, axy,  off);
        awh  += __shfl_down_sync(full, awh,  off);
        aobj += __shfl_down_sync(full, aobj, off);
        acls += __shfl_down_sync(full, acls, off);
        al2  += __shfl_down_sync(full, al2,  off);
    }
    if (lane == 0) {
        sh->red[wid][0]=axy; sh->red[wid][1]=awh; sh->red[wid][2]=aobj;
        sh->red[wid][3]=acls; sh->red[wid][4]=al2;
    }
    __syncthreads();
    if (tid == 0) {
        float s0=0.f,s1=0.f,s2=0.f,s3=0.f,s4=0.f;
        #pragma unroll
        for (int k = 0; k < 8; k++) {
            s0 += sh->red[k][0]; s1 += sh->red[k][1]; s2 += sh->red[k][2];
            s3 += sh->red[k][3]; s4 += sh->red[k][4];
        }
        atomicAdd(&g_acc[0], (double)s0);
        atomicAdd(&g_acc[1], (double)s1);
        atomicAdd(&g_acc[2], (double)s2);
        atomicAdd(&g_acc[3], (double)s3);
        atomicAdd(&g_acc[4], (double)s4);
        __threadfence();
        int old = atomicAdd(&g_cnt, 1);
        if (old == NBLK - 1) {
            float xy  = (float)g_acc[0];
            float wh  = (float)g_acc[1];
            float obj = (float)g_acc[2];
            float cls = (float)g_acc[3];
            float l2  = (float)g_acc[4];
            out[0] = xy + wh + obj + cls;
            out[1] = xy;
            out[2] = wh;
            out[3] = obj;
            out[4] = cls;
            out[5] = l2;
            g_acc[0]=0.0; g_acc[1]=0.0; g_acc[2]=0.0; g_acc[3]=0.0; g_acc[4]=0.0;
            g_cnt = 0;
        }
    }
}

extern "C" void kernel_launch(void* const* d_in, const int* in_sizes, int n_in,
                              void* d_out, int out_size) {
    const float* x0     = (const float*)d_in[0];
    const float* x1     = (const float*)d_in[1];
    const float* x2     = (const float*)d_in[2];
    const float* labels = (const float*)d_in[3];
    float* out = (float*)d_out;
    yolo_k<<<NBLK, 256, sizeof(Sh)>>>(x0, x1, x2, labels, out);
}